// round 1
// baseline (speedup 1.0000x reference)
#include <cuda_runtime.h>
#include <cuda_bf16.h>
#include <math.h>

// ---------------------------------------------------------------------------
// 2-layer LSTM, B=16, T=1024, D=H=512, fp32.
//   gx   = x @ w_ih^T + b_ih          (big GEMM, parallel over B*T)
//   scan = 1024 sequential steps of gates = gx_t + h @ w_hh^T + b_hh
// Output: stacked final h of both layers, (2, 16, 512) fp32.
// ---------------------------------------------------------------------------

#define Bsz   16
#define Tlen  1024
#define Hdim  512
#define G4H   2048
#define NBLK  128          // scan grid (co-resident persistent CTAs)

// Scratch (static device globals; no allocation allowed)
__device__ float g_gx[(size_t)Bsz * Tlen * G4H];     // 128 MiB, reused per layer
__device__ float g_out0[(size_t)Bsz * Tlen * Hdim];  // layer-0 outputs (layer-1 input)
__device__ float g_hbuf[2][Bsz * Hdim];              // ping-pong h exchange
__device__ unsigned int g_bar_count = 0;
__device__ unsigned int g_bar_gen = 0;

// ---- f32x2 packed helpers --------------------------------------------------
union F4U2 { float4 f; ulonglong2 u; };

__device__ __forceinline__ unsigned long long ffma2(unsigned long long a,
                                                    unsigned long long b,
                                                    unsigned long long c) {
    unsigned long long d;
    asm("fma.rn.f32x2 %0, %1, %2, %3;" : "=l"(d) : "l"(a), "l"(b), "l"(c));
    return d;
}
__device__ __forceinline__ unsigned long long dup2(float x) {
    unsigned long long r;
    asm("mov.b64 %0, {%1, %1};" : "=l"(r) : "f"(x));
    return r;
}
__device__ __forceinline__ void unpk2(unsigned long long v, float& lo, float& hi) {
    asm("mov.b64 {%0, %1}, %2;" : "=f"(lo), "=f"(hi) : "l"(v));
}

// ---------------------------------------------------------------------------
// GEMM (NT): C[m,n] = sum_k A[m,k]*B[n,k] + bias[n]
// A: [M,K] row-major, B: [N,K] row-major, K contiguous in both.
// Tiles: 128x128x32, 256 threads, 8x8 micro-tile, f32x2 accumulate.
// M=16384, N=2048, K=512 (all divisible; no bounds checks).
// ---------------------------------------------------------------------------
#define GP 132   // smem row pad (floats), multiple of 4 for float4 loads

__global__ __launch_bounds__(256, 2) void gemm_nt_bias(
    const float* __restrict__ A, const float* __restrict__ B,
    const float* __restrict__ bias, float* __restrict__ C,
    int M, int N, int K)
{
    __shared__ float As[32][GP];
    __shared__ float Bs[32][GP];

    const int tid = threadIdx.x;
    const int m0 = blockIdx.y * 128;
    const int n0 = blockIdx.x * 128;
    const int tx = tid & 15;         // n micro index
    const int ty = tid >> 4;         // m micro index
    const int lrow = tid >> 3;       // 0..31 load row
    const int lkq  = tid & 7;        // 0..7  load k-quad

    unsigned long long acc[8][4];
#pragma unroll
    for (int i = 0; i < 8; i++)
#pragma unroll
        for (int j = 0; j < 4; j++) acc[i][j] = 0ull;

    for (int k0 = 0; k0 < K; k0 += 32) {
#pragma unroll
        for (int i = 0; i < 4; i++) {
            int row = lrow + 32 * i;
            float4 va = *(const float4*)&A[(size_t)(m0 + row) * K + k0 + lkq * 4];
            As[lkq * 4 + 0][row] = va.x;
            As[lkq * 4 + 1][row] = va.y;
            As[lkq * 4 + 2][row] = va.z;
            As[lkq * 4 + 3][row] = va.w;
            float4 vb = *(const float4*)&B[(size_t)(n0 + row) * K + k0 + lkq * 4];
            Bs[lkq * 4 + 0][row] = vb.x;
            Bs[lkq * 4 + 1][row] = vb.y;
            Bs[lkq * 4 + 2][row] = vb.z;
            Bs[lkq * 4 + 3][row] = vb.w;
        }
        __syncthreads();

#pragma unroll
        for (int k = 0; k < 32; k++) {
            float4 a0 = *(const float4*)&As[k][ty * 8];
            float4 a1 = *(const float4*)&As[k][ty * 8 + 4];
            F4U2 b0, b1;
            b0.f = *(const float4*)&Bs[k][tx * 8];
            b1.f = *(const float4*)&Bs[k][tx * 8 + 4];
            unsigned long long bb[4] = { b0.u.x, b0.u.y, b1.u.x, b1.u.y };
            float av[8] = { a0.x, a0.y, a0.z, a0.w, a1.x, a1.y, a1.z, a1.w };
#pragma unroll
            for (int i = 0; i < 8; i++) {
                unsigned long long a2 = dup2(av[i]);
#pragma unroll
                for (int j = 0; j < 4; j++)
                    acc[i][j] = ffma2(a2, bb[j], acc[i][j]);
            }
        }
        __syncthreads();
    }

    float bv[8];
    {
        float4 t0 = *(const float4*)&bias[n0 + tx * 8];
        float4 t1 = *(const float4*)&bias[n0 + tx * 8 + 4];
        bv[0]=t0.x; bv[1]=t0.y; bv[2]=t0.z; bv[3]=t0.w;
        bv[4]=t1.x; bv[5]=t1.y; bv[6]=t1.z; bv[7]=t1.w;
    }
#pragma unroll
    for (int i = 0; i < 8; i++) {
        int row = m0 + ty * 8 + i;
        float v[8];
#pragma unroll
        for (int j = 0; j < 4; j++) unpk2(acc[i][j], v[2 * j], v[2 * j + 1]);
        float4 o0 = make_float4(v[0]+bv[0], v[1]+bv[1], v[2]+bv[2], v[3]+bv[3]);
        float4 o1 = make_float4(v[4]+bv[4], v[5]+bv[5], v[6]+bv[6], v[7]+bv[7]);
        *(float4*)&C[(size_t)row * N + n0 + tx * 8]     = o0;
        *(float4*)&C[(size_t)row * N + n0 + tx * 8 + 4] = o1;
    }
}

// ---------------------------------------------------------------------------
// Recurrent scan: persistent 128-CTA kernel, 1 grid barrier per timestep.
// CTA b owns 4 h-columns; w_hh slice (16 rows x 512) + c stay in smem.
// ---------------------------------------------------------------------------
__device__ __forceinline__ float sigm_(float x) { return 1.0f / (1.0f + expf(-x)); }

// dynamic smem layout (floats):
//   w_s4   : 2048 float4  (16 rows x 128 quads)      32768 B
//   h_s4   : 16*129 float4 (padded rows)             33024 B
//   gate_s : 256 floats                                1024 B
//   gxs_f  : 256 floats (64 float4)                    1024 B
//   c_s    : 64 floats                                  256 B
//   bias_s : 16 floats                                   64 B
#define SCAN_SMEM (32768 + 33024 + 1024 + 1024 + 256 + 64)

__global__ __launch_bounds__(256, 1) void lstm_scan(
    const float* __restrict__ gx,     // [B*T, 4H] (m = b*T + t)
    const float* __restrict__ w_hh,   // [4H, 512]
    const float* __restrict__ b_hh,   // [4H]
    const float* __restrict__ h0,     // [B, 512] (this layer)
    const float* __restrict__ c0,     // [B, 512]
    float* __restrict__ outs,         // [B*T, 512] or nullptr
    float* __restrict__ h_final)      // [B, 512] slice of d_out
{
    extern __shared__ float smem[];
    float4* w_s4   = (float4*)smem;              // 2048
    float4* h_s4   = w_s4 + 2048;                // 2064
    float*  gate_s = (float*)(h_s4 + 2064);      // 256
    float*  gxs_f  = gate_s + 256;               // 256
    float*  c_s    = gxs_f + 256;                // 64
    float*  bias_s = c_s + 64;                   // 16

    const int tid = threadIdx.x;
    const int r   = tid >> 4;        // 0..15 gate-row within CTA  (r = g*4 + jj)
    const int b   = tid & 15;        // batch
    const int jb  = blockIdx.x * 4;  // column base of this CTA

    // ---- persistent preload: w_hh slice, bias, c ----
    const float4* wg4 = (const float4*)w_hh;
#pragma unroll
    for (int i = 0; i < 8; i++) {
        int idx = tid + i * 256;                  // 0..2047
        int rr = idx >> 7, q = idx & 127;
        int grow = ((rr >> 2) * Hdim) + jb + (rr & 3);
        w_s4[idx] = wg4[(size_t)grow * 128 + q];
    }
    if (tid < 16) bias_s[tid] = b_hh[((tid >> 2) * Hdim) + jb + (tid & 3)];
    if (tid < 64) {
        int jj = tid >> 4, bb = tid & 15;
        c_s[tid] = c0[bb * Hdim + jb + jj];
    }
    __syncthreads();

    const unsigned int nblk = gridDim.x;

    for (int t = 0; t < Tlen; t++) {
        // prefetch gx for this step (consumed after the dot product)
        float4 gxv = make_float4(0.f, 0.f, 0.f, 0.f);
        if (tid < 64) {
            int gg = tid >> 4, bb = tid & 15;
            gxv = __ldcg((const float4*)&gx[(size_t)(bb * Tlen + t) * G4H + gg * Hdim + jb]);
        }
        // load current h into smem (L2-coherent: peer CTAs wrote it)
        const float4* hsrc4 = (t == 0) ? (const float4*)h0
                                       : (const float4*)g_hbuf[t & 1];
#pragma unroll
        for (int i = 0; i < 8; i++) {
            int idx = tid + i * 256;              // 0..2047
            int bb = idx >> 7, q = idx & 127;
            h_s4[bb * 129 + q] = __ldcg(&hsrc4[idx]);
        }
        __syncthreads();

        // dot: gates[b, row(r)] = sum_k w[row][k] * h[b][k]
        const float4* wr = w_s4 + r * 128;
        const float4* hr = h_s4 + b * 129;
        unsigned long long a0 = 0, a1 = 0, a2 = 0, a3 = 0;
#pragma unroll 8
        for (int q = 0; q < 64; q++) {
            F4U2 w0, h0v, w1, h1v;
            w0.f = wr[q];      h0v.f = hr[q];
            w1.f = wr[q + 64]; h1v.f = hr[q + 64];
            a0 = ffma2(w0.u.x, h0v.u.x, a0);
            a1 = ffma2(w0.u.y, h0v.u.y, a1);
            a2 = ffma2(w1.u.x, h1v.u.x, a2);
            a3 = ffma2(w1.u.y, h1v.u.y, a3);
        }
        float s0, s1, s2, s3, s4, s5, s6, s7;
        unpk2(a0, s0, s1); unpk2(a1, s2, s3);
        unpk2(a2, s4, s5); unpk2(a3, s6, s7);
        gate_s[r * 16 + b] = ((s0 + s1) + (s2 + s3)) + ((s4 + s5) + (s6 + s7));
        if (tid < 64) *(float4*)&gxs_f[tid * 4] = gxv;
        __syncthreads();

        // elementwise LSTM cell for the 4 owned columns
        if (tid < 64) {
            int jj = tid >> 4, bb = tid & 15;
            float vi = gate_s[(0 + jj) * 16 + bb] + gxs_f[((0  + bb) << 2) + jj] + bias_s[jj];
            float vf = gate_s[(4 + jj) * 16 + bb] + gxs_f[((16 + bb) << 2) + jj] + bias_s[4 + jj];
            float vg = gate_s[(8 + jj) * 16 + bb] + gxs_f[((32 + bb) << 2) + jj] + bias_s[8 + jj];
            float vo = gate_s[(12 + jj) * 16 + bb] + gxs_f[((48 + bb) << 2) + jj] + bias_s[12 + jj];
            float ig = sigm_(vi);
            float fg = sigm_(vf);
            float gg = tanhf(vg);
            float og = sigm_(vo);
            float c  = fg * c_s[tid] + ig * gg;
            c_s[tid] = c;
            float h  = og * tanhf(c);
            int col = jb + jj;
            g_hbuf[(t + 1) & 1][bb * Hdim + col] = h;
            if (outs) outs[(size_t)(bb * Tlen + t) * Hdim + col] = h;
            if (t == Tlen - 1) h_final[bb * Hdim + col] = h;
            __threadfence();
        }

        // ---- grid barrier (all 128 CTAs co-resident) ----
        __syncthreads();
        if (tid == 0) {
            unsigned int gen = atomicAdd(&g_bar_gen, 0u);
            if (atomicAdd(&g_bar_count, 1u) == nblk - 1u) {
                g_bar_count = 0u;
                __threadfence();
                atomicAdd(&g_bar_gen, 1u);
            } else {
                while (*(volatile unsigned int*)&g_bar_gen == gen) { }
            }
        }
        __syncthreads();
    }
}

// ---------------------------------------------------------------------------
extern "C" void kernel_launch(void* const* d_in, const int* in_sizes, int n_in,
                              void* d_out, int out_size)
{
    const float* x     = (const float*)d_in[0];
    const float* h0    = (const float*)d_in[1];   // (2,B,H)
    const float* c0    = (const float*)d_in[2];   // (2,B,H)
    const float* w_ih0 = (const float*)d_in[3];
    const float* w_hh0 = (const float*)d_in[4];
    const float* b_ih0 = (const float*)d_in[5];
    const float* b_hh0 = (const float*)d_in[6];
    const float* w_ih1 = (const float*)d_in[7];
    const float* w_hh1 = (const float*)d_in[8];
    const float* b_ih1 = (const float*)d_in[9];
    const float* b_hh1 = (const float*)d_in[10];
    float* out = (float*)d_out;                   // (2,B,H) = 16384 floats

    void* p;
    cudaGetSymbolAddress(&p, g_gx);   float* gx   = (float*)p;
    cudaGetSymbolAddress(&p, g_out0); float* out0 = (float*)p;

    cudaFuncSetAttribute(lstm_scan, cudaFuncAttributeMaxDynamicSharedMemorySize,
                         SCAN_SMEM);

    const int M = Bsz * Tlen;   // 16384
    dim3 ggrid(G4H / 128, M / 128);  // (16, 128)

    // layer 0
    gemm_nt_bias<<<ggrid, 256>>>(x, w_ih0, b_ih0, gx, M, G4H, Hdim);
    lstm_scan<<<NBLK, 256, SCAN_SMEM>>>(gx, w_hh0, b_hh0,
                                        h0, c0, out0, out);
    // layer 1
    gemm_nt_bias<<<ggrid, 256>>>(out0, w_ih1, b_ih1, gx, M, G4H, Hdim);
    lstm_scan<<<NBLK, 256, SCAN_SMEM>>>(gx, w_hh1, b_hh1,
                                        h0 + Bsz * Hdim, c0 + Bsz * Hdim,
                                        nullptr, out + Bsz * Hdim);
}

// round 2
// speedup vs baseline: 1.2629x; 1.2629x over previous
#include <cuda_runtime.h>
#include <cuda_bf16.h>
#include <math.h>

// ---------------------------------------------------------------------------
// 2-layer LSTM, B=16, T=1024, D=H=512, fp32.
// Round 2: scan rebuilt — W register-resident, h broadcast from smem.
// ---------------------------------------------------------------------------

#define Bsz   16
#define Tlen  1024
#define Hdim  512
#define G4H   2048
#define NBLK  128
#define HPAD  520          // h_s row stride in floats (pad 8 -> conflict-free)

__device__ float g_gx[(size_t)Bsz * Tlen * G4H];
__device__ float g_out0[(size_t)Bsz * Tlen * Hdim];
__device__ float g_hbuf[2][Bsz * Hdim];
__device__ unsigned int g_bar_count = 0;
__device__ unsigned int g_bar_gen = 0;

union F4U2 { float4 f; ulonglong2 u; };
union F2U  { float2 f; unsigned long long u; };

__device__ __forceinline__ unsigned long long ffma2(unsigned long long a,
                                                    unsigned long long b,
                                                    unsigned long long c) {
    unsigned long long d;
    asm("fma.rn.f32x2 %0, %1, %2, %3;" : "=l"(d) : "l"(a), "l"(b), "l"(c));
    return d;
}
__device__ __forceinline__ unsigned long long dup2(float x) {
    unsigned long long r;
    asm("mov.b64 %0, {%1, %1};" : "=l"(r) : "f"(x));
    return r;
}
__device__ __forceinline__ void unpk2(unsigned long long v, float& lo, float& hi) {
    asm("mov.b64 {%0, %1}, %2;" : "=f"(lo), "=f"(hi) : "l"(v));
}

// ---------------------------------------------------------------------------
// GEMM (NT): unchanged from round 1 (≈0.8 ms each); tensor-core port later.
// ---------------------------------------------------------------------------
#define GP 132

__global__ __launch_bounds__(256, 2) void gemm_nt_bias(
    const float* __restrict__ A, const float* __restrict__ B,
    const float* __restrict__ bias, float* __restrict__ C,
    int M, int N, int K)
{
    __shared__ float As[32][GP];
    __shared__ float Bs[32][GP];

    const int tid = threadIdx.x;
    const int m0 = blockIdx.y * 128;
    const int n0 = blockIdx.x * 128;
    const int tx = tid & 15;
    const int ty = tid >> 4;
    const int lrow = tid >> 3;
    const int lkq  = tid & 7;

    unsigned long long acc[8][4];
#pragma unroll
    for (int i = 0; i < 8; i++)
#pragma unroll
        for (int j = 0; j < 4; j++) acc[i][j] = 0ull;

    for (int k0 = 0; k0 < K; k0 += 32) {
#pragma unroll
        for (int i = 0; i < 4; i++) {
            int row = lrow + 32 * i;
            float4 va = *(const float4*)&A[(size_t)(m0 + row) * K + k0 + lkq * 4];
            As[lkq * 4 + 0][row] = va.x;
            As[lkq * 4 + 1][row] = va.y;
            As[lkq * 4 + 2][row] = va.z;
            As[lkq * 4 + 3][row] = va.w;
            float4 vb = *(const float4*)&B[(size_t)(n0 + row) * K + k0 + lkq * 4];
            Bs[lkq * 4 + 0][row] = vb.x;
            Bs[lkq * 4 + 1][row] = vb.y;
            Bs[lkq * 4 + 2][row] = vb.z;
            Bs[lkq * 4 + 3][row] = vb.w;
        }
        __syncthreads();

#pragma unroll
        for (int k = 0; k < 32; k++) {
            float4 a0 = *(const float4*)&As[k][ty * 8];
            float4 a1 = *(const float4*)&As[k][ty * 8 + 4];
            F4U2 b0, b1;
            b0.f = *(const float4*)&Bs[k][tx * 8];
            b1.f = *(const float4*)&Bs[k][tx * 8 + 4];
            unsigned long long bb[4] = { b0.u.x, b0.u.y, b1.u.x, b1.u.y };
            float av[8] = { a0.x, a0.y, a0.z, a0.w, a1.x, a1.y, a1.z, a1.w };
#pragma unroll
            for (int i = 0; i < 8; i++) {
                unsigned long long a2 = dup2(av[i]);
#pragma unroll
                for (int j = 0; j < 4; j++)
                    acc[i][j] = ffma2(a2, bb[j], acc[i][j]);
            }
        }
        __syncthreads();
    }

    float bv[8];
    {
        float4 t0 = *(const float4*)&bias[n0 + tx * 8];
        float4 t1 = *(const float4*)&bias[n0 + tx * 8 + 4];
        bv[0]=t0.x; bv[1]=t0.y; bv[2]=t0.z; bv[3]=t0.w;
        bv[4]=t1.x; bv[5]=t1.y; bv[6]=t1.z; bv[7]=t1.w;
    }
#pragma unroll
    for (int i = 0; i < 8; i++) {
        int row = m0 + ty * 8 + i;
        float v[8];
#pragma unroll
        for (int j = 0; j < 4; j++) unpk2(acc[i][j], v[2 * j], v[2 * j + 1]);
        float4 o0 = make_float4(v[0]+bv[0], v[1]+bv[1], v[2]+bv[2], v[3]+bv[3]);
        float4 o1 = make_float4(v[4]+bv[4], v[5]+bv[5], v[6]+bv[6], v[7]+bv[7]);
        *(float4*)&C[(size_t)row * N + n0 + tx * 8]     = o0;
        *(float4*)&C[(size_t)row * N + n0 + tx * 8 + 4] = o1;
    }
}

// ---------------------------------------------------------------------------
// Scan: 128 persistent CTAs, CTA owns 4 h-columns (16 gate rows) x 16 batches.
// Thread (r=tid&15, ks=tid>>4): W[row(r)][ks*32 .. +32) in 16 f32x2 REGISTERS.
// h_s[b][k] (pad 8). Warp = {2 ks} x {16 r} -> every h LDS.64 is a broadcast.
// ---------------------------------------------------------------------------
__device__ __forceinline__ float sigm_(float x) { return 1.0f / (1.0f + expf(-x)); }

// smem floats: h_s 16*520=8320 | part 16*320=5120 | gate 256 | gxs 256 | c 64 | bias 16
#define SCAN_SMEM ((8320 + 5120 + 256 + 256 + 64 + 16) * 4)

__global__ __launch_bounds__(256, 1) void lstm_scan(
    const float* __restrict__ gx,     // [B*T, 4H]
    const float* __restrict__ w_hh,   // [4H, 512]
    const float* __restrict__ b_hh,   // [4H]
    const float* __restrict__ h0,     // [B, 512]
    const float* __restrict__ c0,     // [B, 512]
    float* __restrict__ outs,         // [B*T, 512] or nullptr
    float* __restrict__ h_final)      // [B, 512]
{
    extern __shared__ float smem[];
    float* h_s    = smem;                  // 8320
    float* part   = h_s + 8320;            // 5120
    float* gate_s = part + 5120;           // 256
    float* gxs_f  = gate_s + 256;          // 256
    float* c_s    = gxs_f + 256;           // 64
    float* bias_s = c_s + 64;              // 16

    const int tid = threadIdx.x;
    const int r   = tid & 15;        // gate-row within CTA (r = g*4 + jj)
    const int ks  = tid >> 4;        // k-slice [ks*32, ks*32+32)
    const int jb  = blockIdx.x * 4;

    // ---- persistent: W slice into registers (16 f32x2 = 32 floats) ----
    unsigned long long w2[16];
    {
        const int grow = (r >> 2) * Hdim + jb + (r & 3);
        const float4* wrow = (const float4*)&w_hh[(size_t)grow * Hdim + ks * 32];
#pragma unroll
        for (int i = 0; i < 8; i++) {
            F4U2 t; t.f = wrow[i];
            w2[2 * i]     = t.u.x;
            w2[2 * i + 1] = t.u.y;
        }
    }
    if (tid < 16) bias_s[tid] = b_hh[(tid >> 2) * Hdim + jb + (tid & 3)];
    if (tid < 64) {
        int jj = tid >> 4, bb = tid & 15;
        c_s[tid] = c0[bb * Hdim + jb + jj];
    }
    __syncthreads();

    const unsigned int nblk = gridDim.x;

    // prefetch gx for t=0
    float4 gxv = make_float4(0.f, 0.f, 0.f, 0.f);
    if (tid < 64) {
        int gg = tid >> 4, bb = tid & 15;
        gxv = __ldcg((const float4*)&gx[(size_t)(bb * Tlen + 0) * G4H + gg * Hdim + jb]);
    }

    for (int t = 0; t < Tlen; t++) {
        // ---- stage h into smem [b][k] (pad rows); no transpose needed ----
        const float4* hsrc4 = (t == 0) ? (const float4*)h0
                                       : (const float4*)g_hbuf[t & 1];
#pragma unroll
        for (int i = 0; i < 8; i++) {
            int idx = tid + i * 256;              // 0..2047
            int bb = idx >> 7, q = idx & 127;
            *(float4*)&h_s[bb * HPAD + 4 * q] = __ldcg(&hsrc4[idx]);
        }
        __syncthreads();

        // ---- dot: acc2[b] += w2[kp] * h[b][ks*32 + 2kp], W in regs ----
        unsigned long long acc2[16];
#pragma unroll
        for (int b = 0; b < 16; b++) acc2[b] = 0ull;

        const float* hk = h_s + ks * 32;
#pragma unroll 4
        for (int kp = 0; kp < 16; kp++) {
#pragma unroll
            for (int b = 0; b < 16; b++) {
                F2U h2; h2.f = *(const float2*)&hk[b * HPAD + 2 * kp];
                acc2[b] = ffma2(w2[kp], h2.u, acc2[b]);
            }
        }

        // ---- partials to smem: part[ks*320 + r*20 + b] ----
        {
            float vals[16];
#pragma unroll
            for (int b = 0; b < 16; b++) {
                float lo, hi; unpk2(acc2[b], lo, hi);
                vals[b] = lo + hi;
            }
            float4* p4 = (float4*)&part[ks * 320 + r * 20];
            p4[0] = make_float4(vals[0], vals[1], vals[2], vals[3]);
            p4[1] = make_float4(vals[4], vals[5], vals[6], vals[7]);
            p4[2] = make_float4(vals[8], vals[9], vals[10], vals[11]);
            p4[3] = make_float4(vals[12], vals[13], vals[14], vals[15]);
        }
        __syncthreads();

        // ---- reduce over ks; thread (r2, b2) owns gate[r2][b2] ----
        {
            int r2 = tid >> 4, b2 = tid & 15;
            float g = 0.f;
#pragma unroll
            for (int k2 = 0; k2 < 16; k2++)
                g += part[k2 * 320 + r2 * 20 + b2];
            gate_s[r2 * 16 + b2] = g;
        }
        if (tid < 64) *(float4*)&gxs_f[tid * 4] = gxv;
        __syncthreads();

        // ---- cell update (4 owned columns x 16 batches) ----
        if (tid < 64) {
            int jj = tid >> 4, bb = tid & 15;
            float vi = gate_s[(0  + jj) * 16 + bb] + gxs_f[((0  + bb) << 2) + jj] + bias_s[jj];
            float vf = gate_s[(4  + jj) * 16 + bb] + gxs_f[((16 + bb) << 2) + jj] + bias_s[4 + jj];
            float vg = gate_s[(8  + jj) * 16 + bb] + gxs_f[((32 + bb) << 2) + jj] + bias_s[8 + jj];
            float vo = gate_s[(12 + jj) * 16 + bb] + gxs_f[((48 + bb) << 2) + jj] + bias_s[12 + jj];
            float ig = sigm_(vi);
            float fg = sigm_(vf);
            float gg = tanhf(vg);
            float og = sigm_(vo);
            float c  = fg * c_s[tid] + ig * gg;
            c_s[tid] = c;
            float h  = og * tanhf(c);
            int col = jb + jj;
            g_hbuf[(t + 1) & 1][bb * Hdim + col] = h;
            if (outs) outs[(size_t)(bb * Tlen + t) * Hdim + col] = h;
            if (t == Tlen - 1) h_final[bb * Hdim + col] = h;
            __threadfence();
        }

        // ---- prefetch gx for t+1 (hides DRAM latency under the barrier) ----
        if (tid < 64 && t + 1 < Tlen) {
            int gg = tid >> 4, bb = tid & 15;
            gxv = __ldcg((const float4*)&gx[(size_t)(bb * Tlen + (t + 1)) * G4H + gg * Hdim + jb]);
        }

        // ---- grid barrier ----
        __syncthreads();
        if (tid == 0) {
            unsigned int gen = atomicAdd(&g_bar_gen, 0u);
            if (atomicAdd(&g_bar_count, 1u) == nblk - 1u) {
                g_bar_count = 0u;
                __threadfence();
                atomicAdd(&g_bar_gen, 1u);
            } else {
                while (*(volatile unsigned int*)&g_bar_gen == gen) { }
            }
        }
        __syncthreads();
    }
}

// ---------------------------------------------------------------------------
extern "C" void kernel_launch(void* const* d_in, const int* in_sizes, int n_in,
                              void* d_out, int out_size)
{
    const float* x     = (const float*)d_in[0];
    const float* h0    = (const float*)d_in[1];
    const float* c0    = (const float*)d_in[2];
    const float* w_ih0 = (const float*)d_in[3];
    const float* w_hh0 = (const float*)d_in[4];
    const float* b_ih0 = (const float*)d_in[5];
    const float* b_hh0 = (const float*)d_in[6];
    const float* w_ih1 = (const float*)d_in[7];
    const float* w_hh1 = (const float*)d_in[8];
    const float* b_ih1 = (const float*)d_in[9];
    const float* b_hh1 = (const float*)d_in[10];
    float* out = (float*)d_out;

    void* p;
    cudaGetSymbolAddress(&p, g_gx);   float* gx   = (float*)p;
    cudaGetSymbolAddress(&p, g_out0); float* out0 = (float*)p;

    cudaFuncSetAttribute(lstm_scan, cudaFuncAttributeMaxDynamicSharedMemorySize,
                         SCAN_SMEM);

    const int M = Bsz * Tlen;
    dim3 ggrid(G4H / 128, M / 128);

    gemm_nt_bias<<<ggrid, 256>>>(x, w_ih0, b_ih0, gx, M, G4H, Hdim);
    lstm_scan<<<NBLK, 256, SCAN_SMEM>>>(gx, w_hh0, b_hh0,
                                        h0, c0, out0, out);
    gemm_nt_bias<<<ggrid, 256>>>(out0, w_ih1, b_ih1, gx, M, G4H, Hdim);
    lstm_scan<<<NBLK, 256, SCAN_SMEM>>>(gx, w_hh1, b_hh1,
                                        h0 + Bsz * Hdim, c0 + Bsz * Hdim,
                                        nullptr, out + Bsz * Hdim);
}